// round 4
// baseline (speedup 1.0000x reference)
#include <cuda_runtime.h>
#include <math.h>

// Problem constants: B=8, H=1024, E=512, V=32000, T=100
#define VOCAB 32000
#define BATCH 8
#define HDIM  1024
#define EDIM  512
#define XV    (HDIM + EDIM)        // 1536
#define XK    (2 * HDIM + EDIM)    // 2560

#define CHUNK   64                 // columns per chunk (16 lanes x 4)
#define NCHUNK  (XV / CHUNK)       // 24
#define WTILES  (VOCAB / 4)        // 8000 tiles of 4 words
#define GRID_MAIN 592              // 148 SMs x 4 CTAs
#define NWARPS_TOTAL (GRID_MAIN * 4)

typedef unsigned long long u64;

__device__ __forceinline__ u64 fma2(u64 a, u64 b, u64 c) {
    u64 d;
    asm("fma.rn.f32x2 %0, %1, %2, %3;" : "=l"(d) : "l"(a), "l"(b), "l"(c));
    return d;
}
__device__ __forceinline__ float f2_lo(u64 a) { return __uint_as_float((unsigned)a); }
__device__ __forceinline__ float f2_hi(u64 a) { return __uint_as_float((unsigned)(a >> 32)); }

// self-resetting dynamic work counters (return to 0 after each launch)
__device__ int g_tile = 0;
__device__ int g_done = 0;

// ---------------------------------------------------------------------------
// Kernel 1: e_v for ALL words: out[b][w] = exp(tanh(x_v[b].W_V[w] + b_V[w]))
// Warp = 4 words. Lanes 0-15: batches 0-3; lanes 16-31: batches 4-7.
// Both halves read identical W addresses (coalesced to one request).
// acc[4 words][4 batches] as f32x2 K-pairs = 32 regs. Depth-2 W pipeline.
// ---------------------------------------------------------------------------
__global__ void __launch_bounds__(128, 4) ev_main_kernel(
    const float* __restrict__ gru,   // [B, H]
    const float* __restrict__ emb,   // [B, E]
    const float* __restrict__ W_V,   // [V, XV]
    const float* __restrict__ b_V,   // [V]
    float* __restrict__ out)         // [B, V]
{
    __shared__ __align__(16) float xs[BATCH][XV];   // 48 KB

    int tid = threadIdx.x;
    for (int i = tid; i < BATCH * XV / 4; i += 128) {
        int idx = i * 4;
        int b = idx / XV;
        int c = idx - b * XV;
        float4 v;
        if (c < HDIM) v = *(const float4*)&gru[b * HDIM + c];
        else          v = *(const float4*)&emb[b * EDIM + (c - HDIM)];
        *(float4*)&xs[b][c] = v;
    }
    __syncthreads();

    int lane  = tid & 31;
    int half  = lane >> 4;         // batch group: 0 -> b0..3, 1 -> b4..7
    int l16   = lane & 15;
    int bbase = half * 4;
    int lc    = l16 * 4;           // column offset within a chunk

    for (;;) {
        int t = 0;
        if (lane == 0) t = atomicAdd(&g_tile, 1);
        t = __shfl_sync(0xffffffffu, t, 0);
        if (t >= WTILES) break;

        int w0 = t * 4;
        const float* W0 = W_V + (size_t)w0 * XV;

        u64 acc[4][4];               // [word][batch]
#pragma unroll
        for (int wi = 0; wi < 4; wi++)
#pragma unroll
            for (int bi = 0; bi < 4; bi++) acc[wi][bi] = 0ull;

        // software pipeline: A = chunk 0, B = chunk 1
        ulonglong2 A[4], B[4];
#pragma unroll
        for (int wi = 0; wi < 4; wi++) {
            A[wi] = *(const ulonglong2*)&W0[(size_t)wi * XV + lc];
            B[wi] = *(const ulonglong2*)&W0[(size_t)wi * XV + CHUNK + lc];
        }

#pragma unroll 4
        for (int p = 0; p < NCHUNK / 2; ++p) {
            int c0 = 2 * p;
            int c1 = 2 * p + 1;

            {   // compute chunk c0 with A, refill A from c0+2
                int c = c0 * CHUNK + lc;
#pragma unroll
                for (int bi = 0; bi < 4; bi++) {
                    ulonglong2 x = *(const ulonglong2*)&xs[bbase + bi][c];
#pragma unroll
                    for (int wi = 0; wi < 4; wi++) {
                        acc[wi][bi] = fma2(A[wi].x, x.x, acc[wi][bi]);
                        acc[wi][bi] = fma2(A[wi].y, x.y, acc[wi][bi]);
                    }
                }
                int nx = c0 + 2 <= NCHUNK - 1 ? c0 + 2 : NCHUNK - 1;
#pragma unroll
                for (int wi = 0; wi < 4; wi++)
                    A[wi] = *(const ulonglong2*)&W0[(size_t)wi * XV + nx * CHUNK + lc];
            }
            {   // compute chunk c1 with B, refill B from c1+2
                int c = c1 * CHUNK + lc;
#pragma unroll
                for (int bi = 0; bi < 4; bi++) {
                    ulonglong2 x = *(const ulonglong2*)&xs[bbase + bi][c];
#pragma unroll
                    for (int wi = 0; wi < 4; wi++) {
                        acc[wi][bi] = fma2(B[wi].x, x.x, acc[wi][bi]);
                        acc[wi][bi] = fma2(B[wi].y, x.y, acc[wi][bi]);
                    }
                }
                int nx = c1 + 2 <= NCHUNK - 1 ? c1 + 2 : NCHUNK - 1;
#pragma unroll
                for (int wi = 0; wi < 4; wi++)
                    B[wi] = *(const ulonglong2*)&W0[(size_t)wi * XV + nx * CHUNK + lc];
            }
        }

        // 16 partials per lane (wi*4+bi); compacting butterfly over the 16
        // lanes of this half-warp (15 shuffles). Lane l16 ends with index l16.
        float v[16];
#pragma unroll
        for (int wi = 0; wi < 4; wi++)
#pragma unroll
            for (int bi = 0; bi < 4; bi++)
                v[wi * 4 + bi] = f2_lo(acc[wi][bi]) + f2_hi(acc[wi][bi]);

#pragma unroll
        for (int d = 8; d > 0; d >>= 1) {
#pragma unroll
            for (int i = 0; i < 16; i++) {
                if (i < d) {
                    float give = (l16 & d) ? v[i] : v[i + d];
                    float got  = __shfl_xor_sync(0xffffffffu, give, d);
                    float keep = (l16 & d) ? v[i + d] : v[i];
                    v[i] = keep + got;
                }
            }
        }

        int wi   = l16 >> 2;
        int bi   = l16 & 3;
        int word = w0 + wi;
        int b    = bbase + bi;
        float e  = v[0] + b_V[word];
        out[(size_t)b * VOCAB + word] = expf(tanhf(e));
    }

    if (lane == 0) {
        int d = atomicAdd(&g_done, 1);
        if (d == NWARPS_TOTAL - 1) {
            g_tile = 0;
            __threadfence();
            g_done = 0;
        }
    }
}

// ---------------------------------------------------------------------------
// Kernel 2: per-row fixup + softmax normalize. CTA b owns row b.
// Phase 1: overwrite topic-word entries with exp(tanh(k * e_k)).
// Phase 2: sum row, normalize (tanh-bounded => no max pass).
// ---------------------------------------------------------------------------
__global__ void __launch_bounds__(1024) finish_kernel(
    const float* __restrict__ gru,
    const float* __restrict__ emb,
    const float* __restrict__ ctx,
    const int*   __restrict__ topic, // [B, T]
    int T,
    const float* __restrict__ W_K,   // [V, XK]
    const float* __restrict__ b_K,   // [V]
    float* __restrict__ out)         // [B, V]
{
    __shared__ __align__(16) float xk[XK];   // 10 KB: x_k for this row
    __shared__ float red[32];

    int b    = blockIdx.x;
    int tid  = threadIdx.x;
    int lane = tid & 31;
    int wid  = tid >> 5;

    // cache x_k[b] = [gru | emb | ctx]
    for (int i = tid; i < XK / 4; i += 1024) {
        int c = i * 4;
        float4 v;
        if (c < HDIM)      v = *(const float4*)&gru[b * HDIM + c];
        else if (c < XV)   v = *(const float4*)&emb[b * EDIM + (c - HDIM)];
        else               v = *(const float4*)&ctx[b * HDIM + (c - XV)];
        *(float4*)&xk[c] = v;
    }
    __syncthreads();

    // Phase 1: one warp per topic slot (strided). Duplicates write identical
    // values (benign race).
    for (int t = wid; t < T; t += 32) {
        int w = topic[b * T + t];
        if (w == 0) continue;

        int cnt = 0;
        for (int tt = lane; tt < T; tt += 32)
            cnt += (topic[b * T + tt] == w) ? 1 : 0;
#pragma unroll
        for (int o = 16; o > 0; o >>= 1)
            cnt += __shfl_xor_sync(0xffffffffu, cnt, o);

        const float* Wr = W_K + (size_t)w * XK;
        float s = 0.0f;
#pragma unroll
        for (int c = lane * 4; c < XK; c += 128) {
            float4 wv = *(const float4*)&Wr[c];
            float4 xv = *(const float4*)&xk[c];
            s += wv.x * xv.x + wv.y * xv.y + wv.z * xv.z + wv.w * xv.w;
        }
#pragma unroll
        for (int o = 16; o > 0; o >>= 1)
            s += __shfl_xor_sync(0xffffffffu, s, o);

        if (lane == 0) {
            float e = (float)cnt * (s + b_K[w]);
            out[(size_t)b * VOCAB + w] = expf(tanhf(e));
        }
    }
    __syncthreads();

    // Phase 2: sum + normalize
    float* row = out + (size_t)b * VOCAB;
    float s = 0.0f;
    for (int i = tid * 4; i < VOCAB; i += 1024 * 4) {
        float4 v = *(const float4*)&row[i];
        s += (v.x + v.y) + (v.z + v.w);
    }
#pragma unroll
    for (int o = 16; o > 0; o >>= 1)
        s += __shfl_xor_sync(0xffffffffu, s, o);
    if (lane == 0) red[wid] = s;
    __syncthreads();
    if (wid == 0) {
        s = red[lane];
#pragma unroll
        for (int o = 16; o > 0; o >>= 1)
            s += __shfl_xor_sync(0xffffffffu, s, o);
        if (lane == 0) red[0] = s;
    }
    __syncthreads();

    float inv = 1.0f / red[0];
    for (int i = tid * 4; i < VOCAB; i += 1024 * 4) {
        float4 v = *(const float4*)&row[i];
        v.x *= inv; v.y *= inv; v.z *= inv; v.w *= inv;
        *(float4*)&row[i] = v;
    }
}

// ---------------------------------------------------------------------------
extern "C" void kernel_launch(void* const* d_in, const int* in_sizes, int n_in,
                              void* d_out, int out_size)
{
    const float* gru   = (const float*)d_in[0];
    const float* emb   = (const float*)d_in[1];
    const float* ctx   = (const float*)d_in[2];
    const int*   topic = (const int*)d_in[3];
    int T = in_sizes[3] / BATCH;

    const float* W_V = nullptr; const float* b_V = nullptr;
    const float* W_K = nullptr; const float* b_K = nullptr;
    for (int i = 4; i < n_in; ++i) {
        long sz = (long)in_sizes[i];
        if (sz == (long)VOCAB * XV && i + 1 < n_in) {
            W_V = (const float*)d_in[i];
            b_V = (const float*)d_in[i + 1];
        } else if (sz == (long)VOCAB * XK && i + 1 < n_in) {
            W_K = (const float*)d_in[i];
            b_K = (const float*)d_in[i + 1];
        }
    }

    float* out = (float*)d_out;

    ev_main_kernel<<<GRID_MAIN, 128>>>(gru, emb, W_V, b_V, out);
    finish_kernel<<<BATCH, 1024>>>(gru, emb, ctx, topic, T, W_K, b_K, out);
}

// round 5
// speedup vs baseline: 1.1704x; 1.1704x over previous
#include <cuda_runtime.h>
#include <math.h>

// Problem constants: B=8, H=1024, E=512, V=32000, T=100
#define VOCAB 32000
#define BATCH 8
#define HDIM  1024
#define EDIM  512
#define XV    (HDIM + EDIM)        // 1536
#define XK    (2 * HDIM + EDIM)    // 2560

#define CHUNK   64                 // columns per chunk (16 lanes x 4)
#define NCHUNK  (XV / CHUNK)       // 24
#define WTILES  (VOCAB / 4)        // 8000 tiles of 4 words
#define GRID_MAIN 592              // 148 SMs x 4 CTAs
#define NWARPS_TOTAL (GRID_MAIN * 4)
#define NORM_SLICES 16             // normalize: CTAs per row
#define NORM_GRID (BATCH * NORM_SLICES)

typedef unsigned long long u64;

__device__ __forceinline__ u64 fma2(u64 a, u64 b, u64 c) {
    u64 d;
    asm("fma.rn.f32x2 %0, %1, %2, %3;" : "=l"(d) : "l"(a), "l"(b), "l"(c));
    return d;
}
__device__ __forceinline__ float f2_lo(u64 a) { return __uint_as_float((unsigned)a); }
__device__ __forceinline__ float f2_hi(u64 a) { return __uint_as_float((unsigned)(a >> 32)); }

// self-resetting device state (all zero at load; every launch sequence
// returns them to zero, so graph replays are deterministic)
__device__ int   g_tile = 0;
__device__ int   g_done = 0;
__device__ float g_rowsum[BATCH] = {};
__device__ int   g_norm_done = 0;

// ---------------------------------------------------------------------------
// Kernel 1: e_v for ALL words: out[b][w] = exp(tanh(x_v[b].W_V[w] + b_V[w]))
// Warp = 4 words. Lanes 0-15: batches 0-3; lanes 16-31: batches 4-7 (both
// halves read identical W addresses -> one coalesced request).
// Each thread also accumulates the sum of its exp outputs (its batch index
// is fixed) -> per-row softmax denominators via 8 atomics per CTA.
// ---------------------------------------------------------------------------
__global__ void __launch_bounds__(128, 4) ev_main_kernel(
    const float* __restrict__ gru,   // [B, H]
    const float* __restrict__ emb,   // [B, E]
    const float* __restrict__ W_V,   // [V, XV]
    const float* __restrict__ b_V,   // [V]
    float* __restrict__ out)         // [B, V]
{
    __shared__ __align__(16) float xs[BATCH][XV];   // 48 KB
    __shared__ float rs[BATCH];

    int tid = threadIdx.x;
    if (tid < BATCH) rs[tid] = 0.0f;
    for (int i = tid; i < BATCH * XV / 4; i += 128) {
        int idx = i * 4;
        int b = idx / XV;
        int c = idx - b * XV;
        float4 v;
        if (c < HDIM) v = *(const float4*)&gru[b * HDIM + c];
        else          v = *(const float4*)&emb[b * EDIM + (c - HDIM)];
        *(float4*)&xs[b][c] = v;
    }
    __syncthreads();

    int lane  = tid & 31;
    int half  = lane >> 4;         // batch group: 0 -> b0..3, 1 -> b4..7
    int l16   = lane & 15;
    int bbase = half * 4;
    int lc    = l16 * 4;
    int myb   = bbase + (l16 & 3); // this thread's output batch (fixed)
    float rsum = 0.0f;

    for (;;) {
        int t = 0;
        if (lane == 0) t = atomicAdd(&g_tile, 1);
        t = __shfl_sync(0xffffffffu, t, 0);
        if (t >= WTILES) break;

        int w0 = t * 4;
        const float* W0 = W_V + (size_t)w0 * XV;

        u64 acc[4][4];               // [word][batch]
#pragma unroll
        for (int wi = 0; wi < 4; wi++)
#pragma unroll
            for (int bi = 0; bi < 4; bi++) acc[wi][bi] = 0ull;

        ulonglong2 A[4], B[4];
#pragma unroll
        for (int wi = 0; wi < 4; wi++) {
            A[wi] = *(const ulonglong2*)&W0[(size_t)wi * XV + lc];
            B[wi] = *(const ulonglong2*)&W0[(size_t)wi * XV + CHUNK + lc];
        }

#pragma unroll 4
        for (int p = 0; p < NCHUNK / 2; ++p) {
            int c0 = 2 * p;
            int c1 = 2 * p + 1;
            {
                int c = c0 * CHUNK + lc;
#pragma unroll
                for (int bi = 0; bi < 4; bi++) {
                    ulonglong2 x = *(const ulonglong2*)&xs[bbase + bi][c];
#pragma unroll
                    for (int wi = 0; wi < 4; wi++) {
                        acc[wi][bi] = fma2(A[wi].x, x.x, acc[wi][bi]);
                        acc[wi][bi] = fma2(A[wi].y, x.y, acc[wi][bi]);
                    }
                }
                int nx = c0 + 2 <= NCHUNK - 1 ? c0 + 2 : NCHUNK - 1;
#pragma unroll
                for (int wi = 0; wi < 4; wi++)
                    A[wi] = *(const ulonglong2*)&W0[(size_t)wi * XV + nx * CHUNK + lc];
            }
            {
                int c = c1 * CHUNK + lc;
#pragma unroll
                for (int bi = 0; bi < 4; bi++) {
                    ulonglong2 x = *(const ulonglong2*)&xs[bbase + bi][c];
#pragma unroll
                    for (int wi = 0; wi < 4; wi++) {
                        acc[wi][bi] = fma2(B[wi].x, x.x, acc[wi][bi]);
                        acc[wi][bi] = fma2(B[wi].y, x.y, acc[wi][bi]);
                    }
                }
                int nx = c1 + 2 <= NCHUNK - 1 ? c1 + 2 : NCHUNK - 1;
#pragma unroll
                for (int wi = 0; wi < 4; wi++)
                    B[wi] = *(const ulonglong2*)&W0[(size_t)wi * XV + nx * CHUNK + lc];
            }
        }

        float v[16];
#pragma unroll
        for (int wi = 0; wi < 4; wi++)
#pragma unroll
            for (int bi = 0; bi < 4; bi++)
                v[wi * 4 + bi] = f2_lo(acc[wi][bi]) + f2_hi(acc[wi][bi]);

#pragma unroll
        for (int d = 8; d > 0; d >>= 1) {
#pragma unroll
            for (int i = 0; i < 16; i++) {
                if (i < d) {
                    float give = (l16 & d) ? v[i] : v[i + d];
                    float got  = __shfl_xor_sync(0xffffffffu, give, d);
                    float keep = (l16 & d) ? v[i + d] : v[i];
                    v[i] = keep + got;
                }
            }
        }

        int wi   = l16 >> 2;
        int word = w0 + wi;
        float u  = expf(tanhf(v[0] + b_V[word]));
        out[(size_t)myb * VOCAB + word] = u;
        rsum += u;
    }

    // per-CTA row-sum reduction -> 8 global atomics
    atomicAdd(&rs[myb], rsum);
    __syncthreads();
    if (tid < BATCH) atomicAdd(&g_rowsum[tid], rs[tid]);

    if (lane == 0) {
        int d = atomicAdd(&g_done, 1);
        if (d == NWARPS_TOTAL - 1) {
            g_tile = 0;
            __threadfence();
            g_done = 0;
        }
    }
}

// ---------------------------------------------------------------------------
// Kernel 2: fixup topic words (k>0 => v=0 => energy = tanh(k*e_k)).
// One warp per (b,t); only the FIRST occurrence of each word acts (dedup),
// and it also adjusts the row sum by (new - old).
// ---------------------------------------------------------------------------
__global__ void __launch_bounds__(256) ek_fixup_kernel(
    const float* __restrict__ gru,
    const float* __restrict__ emb,
    const float* __restrict__ ctx,
    const int*   __restrict__ topic, // [B, T]
    int T,
    const float* __restrict__ W_K,   // [V, XK]
    const float* __restrict__ b_K,   // [V]
    float* __restrict__ out)
{
    int gw   = (int)((blockIdx.x * blockDim.x + threadIdx.x) >> 5);
    int lane = threadIdx.x & 31;
    if (gw >= BATCH * T) return;
    int b = gw / T;
    int t = gw - b * T;

    int w = topic[b * T + t];
    if (w == 0) return;

    // count occurrences + find first occurrence index (dedup)
    int cnt = 0, first = T;
    for (int tt = lane; tt < T; tt += 32) {
        if (topic[b * T + tt] == w) {
            cnt += 1;
            if (tt < first) first = tt;
        }
    }
#pragma unroll
    for (int o = 16; o > 0; o >>= 1) {
        cnt += __shfl_xor_sync(0xffffffffu, cnt, o);
        int of = __shfl_xor_sync(0xffffffffu, first, o);
        first = of < first ? of : first;
    }
    if (first != t) return;          // another warp owns this word

    const float* Wr = W_K + (size_t)w * XK;
    float s = 0.0f;
#pragma unroll
    for (int c = lane * 4; c < XK; c += 128) {
        float4 wv = *(const float4*)&Wr[c];
        float4 xv;
        if (c < HDIM)      xv = *(const float4*)&gru[b * HDIM + c];
        else if (c < XV)   xv = *(const float4*)&emb[b * EDIM + (c - HDIM)];
        else               xv = *(const float4*)&ctx[b * HDIM + (c - XV)];
        s += wv.x * xv.x + wv.y * xv.y + wv.z * xv.z + wv.w * xv.w;
    }
#pragma unroll
    for (int o = 16; o > 0; o >>= 1)
        s += __shfl_xor_sync(0xffffffffu, s, o);

    if (lane == 0) {
        float e   = (float)cnt * (s + b_K[w]);
        float nu  = expf(tanhf(e));
        size_t ix = (size_t)b * VOCAB + w;
        float old = out[ix];
        out[ix] = nu;
        atomicAdd(&g_rowsum[b], nu - old);
    }
}

// ---------------------------------------------------------------------------
// Kernel 3: scale by 1/rowsum. Grid = 8 rows x 16 slices. Last CTA resets
// g_rowsum for the next graph replay.
// ---------------------------------------------------------------------------
__global__ void __launch_bounds__(256) norm_kernel(float* __restrict__ out)
{
    int b     = blockIdx.x / NORM_SLICES;
    int slice = blockIdx.x % NORM_SLICES;
    float inv = 1.0f / g_rowsum[b];

    const int per = VOCAB / NORM_SLICES;          // 2000
    float* seg = out + (size_t)b * VOCAB + slice * per;
    for (int i = threadIdx.x * 4; i < per; i += 256 * 4) {
        float4 v = *(const float4*)&seg[i];
        v.x *= inv; v.y *= inv; v.z *= inv; v.w *= inv;
        *(float4*)&seg[i] = v;
    }

    __syncthreads();
    if (threadIdx.x == 0) {
        int d = atomicAdd(&g_norm_done, 1);
        if (d == NORM_GRID - 1) {
            for (int i = 0; i < BATCH; i++) g_rowsum[i] = 0.0f;
            __threadfence();
            g_norm_done = 0;
        }
    }
}

// ---------------------------------------------------------------------------
extern "C" void kernel_launch(void* const* d_in, const int* in_sizes, int n_in,
                              void* d_out, int out_size)
{
    const float* gru   = (const float*)d_in[0];
    const float* emb   = (const float*)d_in[1];
    const float* ctx   = (const float*)d_in[2];
    const int*   topic = (const int*)d_in[3];
    int T = in_sizes[3] / BATCH;

    const float* W_V = nullptr; const float* b_V = nullptr;
    const float* W_K = nullptr; const float* b_K = nullptr;
    for (int i = 4; i < n_in; ++i) {
        long sz = (long)in_sizes[i];
        if (sz == (long)VOCAB * XV && i + 1 < n_in) {
            W_V = (const float*)d_in[i];
            b_V = (const float*)d_in[i + 1];
        } else if (sz == (long)VOCAB * XK && i + 1 < n_in) {
            W_K = (const float*)d_in[i];
            b_K = (const float*)d_in[i + 1];
        }
    }

    float* out = (float*)d_out;

    ev_main_kernel<<<GRID_MAIN, 128>>>(gru, emb, W_V, b_V, out);

    int nwarps  = BATCH * T;
    int nblocks = (nwarps * 32 + 255) / 256;
    ek_fixup_kernel<<<nblocks, 256>>>(gru, emb, ctx, topic, T, W_K, b_K, out);

    norm_kernel<<<NORM_GRID, 256>>>(out);
}

// round 6
// speedup vs baseline: 1.1770x; 1.0057x over previous
#include <cuda_runtime.h>
#include <math.h>

// Problem constants: B=8, H=1024, E=512, V=32000, T=100
#define VOCAB 32000
#define BATCH 8
#define HDIM  1024
#define EDIM  512
#define XV    (HDIM + EDIM)        // 1536
#define XK    (2 * HDIM + EDIM)    // 2560

#define CHUNK   64                 // columns per chunk (16 lanes x 4)
#define NCHUNK  (XV / CHUNK)       // 24
#define WTILES  (VOCAB / 4)        // 8000 tiles of 4 words
#define GRID_MAIN 592              // 148 SMs x 4 CTAs
#define NWARPS_TOTAL (GRID_MAIN * 4)
#define NORM_SLICES 16
#define NORM_GRID (BATCH * NORM_SLICES)

typedef unsigned long long u64;

__device__ __forceinline__ u64 fma2(u64 a, u64 b, u64 c) {
    u64 d;
    asm("fma.rn.f32x2 %0, %1, %2, %3;" : "=l"(d) : "l"(a), "l"(b), "l"(c));
    return d;
}
__device__ __forceinline__ float f2_lo(u64 a) { return __uint_as_float((unsigned)a); }
__device__ __forceinline__ float f2_hi(u64 a) { return __uint_as_float((unsigned)(a >> 32)); }

// exp(tanh(e)) with fast intrinsics; clamp keeps __expf finite (tanh(9) == 1
// to fp32 anyway). Max abs err ~1e-6 on the output, fine vs 1e-3 threshold.
__device__ __forceinline__ float exp_tanh(float e) {
    float ec = fminf(fmaxf(e, -9.0f), 9.0f);
    float t  = __expf(2.0f * ec);
    float th = (t - 1.0f) / (t + 1.0f);
    return __expf(th);
}

// self-resetting device state (zero at load; each launch returns it to zero)
__device__ int   g_tile = 0;
__device__ int   g_done = 0;
__device__ float g_rowsum[BATCH] = {};
__device__ int   g_norm_done = 0;

// ---------------------------------------------------------------------------
// Kernel 1: e_v for ALL words. Warp = 4 words; lanes 0-15 accumulate batches
// 0-3, lanes 16-31 batches 4-7 (identical W addresses -> coalesced).
// Depth-3 register pipeline (12 LDG.128 in flight / thread), overlapped
// atomic tile fetch, on-the-fly row sums.
// ---------------------------------------------------------------------------
__global__ void __launch_bounds__(128, 4) ev_main_kernel(
    const float* __restrict__ gru,   // [B, H]
    const float* __restrict__ emb,   // [B, E]
    const float* __restrict__ W_V,   // [V, XV]
    const float* __restrict__ b_V,   // [V]
    float* __restrict__ out)         // [B, V]
{
    __shared__ __align__(16) float xs[BATCH][XV];   // 48 KB
    __shared__ float rs[BATCH];

    int tid = threadIdx.x;
    if (tid < BATCH) rs[tid] = 0.0f;
    for (int i = tid; i < BATCH * XV / 4; i += 128) {
        int idx = i * 4;
        int b = idx / XV;
        int c = idx - b * XV;
        float4 v;
        if (c < HDIM) v = *(const float4*)&gru[b * HDIM + c];
        else          v = *(const float4*)&emb[b * EDIM + (c - HDIM)];
        *(float4*)&xs[b][c] = v;
    }
    __syncthreads();

    int lane  = tid & 31;
    int half  = lane >> 4;
    int l16   = lane & 15;
    int bbase = half * 4;
    int lc    = l16 * 4;
    int myb   = bbase + (l16 & 3);
    float rsum = 0.0f;

    int t = 0;
    if (lane == 0) t = atomicAdd(&g_tile, 1);
    t = __shfl_sync(0xffffffffu, t, 0);

    while (t < WTILES) {
        int w0 = t * 4;
        const float* W0 = W_V + (size_t)w0 * XV + lc;   // wi*XV folds to LDG imm

        // depth-3 prefetch: chunks 0,1,2
        ulonglong2 A[4], B[4], C[4];
#pragma unroll
        for (int wi = 0; wi < 4; wi++) {
            A[wi] = *(const ulonglong2*)&W0[wi * XV + 0 * CHUNK];
            B[wi] = *(const ulonglong2*)&W0[wi * XV + 1 * CHUNK];
            C[wi] = *(const ulonglong2*)&W0[wi * XV + 2 * CHUNK];
        }

        // fetch NEXT tile index now; ~320cyc atomic latency hides under compute
        int tn = 0;
        if (lane == 0) tn = atomicAdd(&g_tile, 1);

        u64 acc[4][4];
#pragma unroll
        for (int wi = 0; wi < 4; wi++)
#pragma unroll
            for (int bi = 0; bi < 4; bi++) acc[wi][bi] = 0ull;

#pragma unroll
        for (int p = 0; p < NCHUNK / 3; ++p) {          // 8 macro-iters
#pragma unroll
            for (int s = 0; s < 3; ++s) {
                int cc = 3 * p + s;
                ulonglong2* buf = (s == 0) ? A : (s == 1) ? B : C;
                int c = cc * CHUNK + lc;
#pragma unroll
                for (int bi = 0; bi < 4; bi++) {
                    ulonglong2 x = *(const ulonglong2*)&xs[bbase + bi][c];
#pragma unroll
                    for (int wi = 0; wi < 4; wi++) {
                        acc[wi][bi] = fma2(buf[wi].x, x.x, acc[wi][bi]);
                        acc[wi][bi] = fma2(buf[wi].y, x.y, acc[wi][bi]);
                    }
                }
                int nx = cc + 3 <= NCHUNK - 1 ? cc + 3 : NCHUNK - 1;
#pragma unroll
                for (int wi = 0; wi < 4; wi++)
                    buf[wi] = *(const ulonglong2*)&W0[wi * XV + nx * CHUNK];
            }
        }

        // 16 partials per lane (wi*4+bi); compacting butterfly across the
        // 16 lanes of this half-warp. Lane l16 ends holding index l16.
        float v[16];
#pragma unroll
        for (int wi = 0; wi < 4; wi++)
#pragma unroll
            for (int bi = 0; bi < 4; bi++)
                v[wi * 4 + bi] = f2_lo(acc[wi][bi]) + f2_hi(acc[wi][bi]);

#pragma unroll
        for (int d = 8; d > 0; d >>= 1) {
#pragma unroll
            for (int i = 0; i < 16; i++) {
                if (i < d) {
                    float give = (l16 & d) ? v[i] : v[i + d];
                    float got  = __shfl_xor_sync(0xffffffffu, give, d);
                    float keep = (l16 & d) ? v[i + d] : v[i];
                    v[i] = keep + got;
                }
            }
        }

        int wi   = l16 >> 2;
        int word = w0 + wi;
        float u  = exp_tanh(v[0] + __ldg(&b_V[word]));
        out[(size_t)myb * VOCAB + word] = u;
        rsum += u;

        t = __shfl_sync(0xffffffffu, tn, 0);
    }

    atomicAdd(&rs[myb], rsum);
    __syncthreads();
    if (tid < BATCH) atomicAdd(&g_rowsum[tid], rs[tid]);

    if (lane == 0) {
        int d = atomicAdd(&g_done, 1);
        if (d == NWARPS_TOTAL - 1) {
            g_tile = 0;
            __threadfence();
            g_done = 0;
        }
    }
}

// ---------------------------------------------------------------------------
// Kernel 2: fixup topic words (k>0 => v=0 => energy = tanh(k*e_k)).
// One warp per (b,t); only the FIRST occurrence acts (dedup) and adjusts
// the row sum by (new - old). Dot loop fully unrolled -> 20 LDG.128 in
// flight per lane.
// ---------------------------------------------------------------------------
__global__ void __launch_bounds__(256) ek_fixup_kernel(
    const float* __restrict__ gru,
    const float* __restrict__ emb,
    const float* __restrict__ ctx,
    const int*   __restrict__ topic, // [B, T]
    int T,
    const float* __restrict__ W_K,   // [V, XK]
    const float* __restrict__ b_K,   // [V]
    float* __restrict__ out)
{
    int gw   = (int)((blockIdx.x * blockDim.x + threadIdx.x) >> 5);
    int lane = threadIdx.x & 31;
    if (gw >= BATCH * T) return;
    int b = gw / T;
    int t = gw - b * T;

    int w = topic[b * T + t];
    if (w == 0) return;

    int cnt = 0, first = T;
    for (int tt = lane; tt < T; tt += 32) {
        if (topic[b * T + tt] == w) {
            cnt += 1;
            if (tt < first) first = tt;
        }
    }
#pragma unroll
    for (int o = 16; o > 0; o >>= 1) {
        cnt += __shfl_xor_sync(0xffffffffu, cnt, o);
        int of = __shfl_xor_sync(0xffffffffu, first, o);
        first = of < first ? of : first;
    }
    if (first != t) return;

    const float* Wr = W_K + (size_t)w * XK + lane * 4;
    const int cbase = lane * 4;
    float s = 0.0f;
#pragma unroll
    for (int j = 0; j < XK / 128; ++j) {            // 20 fixed iterations
        int c = cbase + j * 128;
        float4 wv = *(const float4*)&Wr[j * 128];
        float4 xv;
        if (c < HDIM)      xv = *(const float4*)&gru[b * HDIM + c];
        else if (c < XV)   xv = *(const float4*)&emb[b * EDIM + (c - HDIM)];
        else               xv = *(const float4*)&ctx[b * HDIM + (c - XV)];
        s += wv.x * xv.x + wv.y * xv.y + wv.z * xv.z + wv.w * xv.w;
    }
#pragma unroll
    for (int o = 16; o > 0; o >>= 1)
        s += __shfl_xor_sync(0xffffffffu, s, o);

    if (lane == 0) {
        float e   = (float)cnt * (s + b_K[w]);
        float nu  = exp_tanh(e);
        size_t ix = (size_t)b * VOCAB + w;
        float old = out[ix];
        out[ix] = nu;
        atomicAdd(&g_rowsum[b], nu - old);
    }
}

// ---------------------------------------------------------------------------
// Kernel 3: scale by 1/rowsum; last CTA resets g_rowsum for next replay.
// ---------------------------------------------------------------------------
__global__ void __launch_bounds__(256) norm_kernel(float* __restrict__ out)
{
    int b     = blockIdx.x / NORM_SLICES;
    int slice = blockIdx.x % NORM_SLICES;
    float inv = 1.0f / g_rowsum[b];

    const int per = VOCAB / NORM_SLICES;          // 2000
    float* seg = out + (size_t)b * VOCAB + slice * per;
    for (int i = threadIdx.x * 4; i < per; i += 256 * 4) {
        float4 v = *(const float4*)&seg[i];
        v.x *= inv; v.y *= inv; v.z *= inv; v.w *= inv;
        *(float4*)&seg[i] = v;
    }

    __syncthreads();
    if (threadIdx.x == 0) {
        int d = atomicAdd(&g_norm_done, 1);
        if (d == NORM_GRID - 1) {
            for (int i = 0; i < BATCH; i++) g_rowsum[i] = 0.0f;
            __threadfence();
            g_norm_done = 0;
        }
    }
}

// ---------------------------------------------------------------------------
extern "C" void kernel_launch(void* const* d_in, const int* in_sizes, int n_in,
                              void* d_out, int out_size)
{
    const float* gru   = (const float*)d_in[0];
    const float* emb   = (const float*)d_in[1];
    const float* ctx   = (const float*)d_in[2];
    const int*   topic = (const int*)d_in[3];
    int T = in_sizes[3] / BATCH;

    const float* W_V = nullptr; const float* b_V = nullptr;
    const float* W_K = nullptr; const float* b_K = nullptr;
    for (int i = 4; i < n_in; ++i) {
        long sz = (long)in_sizes[i];
        if (sz == (long)VOCAB * XV && i + 1 < n_in) {
            W_V = (const float*)d_in[i];
            b_V = (const float*)d_in[i + 1];
        } else if (sz == (long)VOCAB * XK && i + 1 < n_in) {
            W_K = (const float*)d_in[i];
            b_K = (const float*)d_in[i + 1];
        }
    }

    float* out = (float*)d_out;

    ev_main_kernel<<<GRID_MAIN, 128>>>(gru, emb, W_V, b_V, out);

    int nwarps  = BATCH * T;
    int nblocks = (nwarps * 32 + 255) / 256;
    ek_fixup_kernel<<<nblocks, 256>>>(gru, emb, ctx, topic, T, W_K, b_K, out);

    norm_kernel<<<NORM_GRID, 256>>>(out);
}

// round 7
// speedup vs baseline: 1.2335x; 1.0480x over previous
#include <cuda_runtime.h>
#include <math.h>

// Problem constants: B=8, H=1024, E=512, V=32000, T=100
#define VOCAB 32000
#define BATCH 8
#define HDIM  1024
#define EDIM  512
#define XV    (HDIM + EDIM)        // 1536
#define XK    (2 * HDIM + EDIM)    // 2560

#define NW      8                  // words per warp-tile
#define TILES   (VOCAB / NW)       // 4000
#define DEPTH   3                  // cp.async ring stages per warp
#define STAGEF  (NW * 64)          // floats per stage (8 words x 64 cols) = 2KB
#define NSTAGES (XV / 64)          // 24 column-chunks of 64
#define CTAS    296                // 148 SMs x 2 CTAs
#define WARPS_PER_CTA 8
#define NWARPS_TOTAL (CTAS * WARPS_PER_CTA)
#define NORM_SLICES 16
#define NORM_GRID (BATCH * NORM_SLICES)

// dynamic smem: xs[8][1536] | rings[8 warps][DEPTH][STAGEF] | rs[8]
#define SMEM_FLOATS (BATCH * XV + WARPS_PER_CTA * DEPTH * STAGEF + 8)
#define SMEM_BYTES  (SMEM_FLOATS * 4)

typedef unsigned long long u64;

__device__ __forceinline__ u64 fma2(u64 a, u64 b, u64 c) {
    u64 d;
    asm("fma.rn.f32x2 %0, %1, %2, %3;" : "=l"(d) : "l"(a), "l"(b), "l"(c));
    return d;
}
__device__ __forceinline__ float f2_lo(u64 a) { return __uint_as_float((unsigned)a); }
__device__ __forceinline__ float f2_hi(u64 a) { return __uint_as_float((unsigned)(a >> 32)); }

__device__ __forceinline__ float exp_tanh(float e) {
    float ec = fminf(fmaxf(e, -9.0f), 9.0f);
    float t  = __expf(2.0f * ec);
    float th = (t - 1.0f) / (t + 1.0f);
    return __expf(th);
}

__device__ __forceinline__ void cp16(float* smem_dst, const float* gmem_src) {
    unsigned s = (unsigned)__cvta_generic_to_shared(smem_dst);
    asm volatile("cp.async.cg.shared.global [%0], [%1], 16;\n"
                 :: "r"(s), "l"(gmem_src) : "memory");
}
#define CP_COMMIT() asm volatile("cp.async.commit_group;\n" ::: "memory")
#define CP_WAIT(N)  asm volatile("cp.async.wait_group %0;\n" :: "n"(N) : "memory")

// self-resetting device state
__device__ int   g_tile = 0;
__device__ int   g_done = 0;
__device__ float g_rowsum[BATCH] = {};
__device__ int   g_norm_done = 0;

// 16-value compacting butterfly across a half-warp (15 shuffles).
// Lane l16 ends up holding the full sum for index l16.
__device__ __forceinline__ float reduce16(float* v, int l16) {
#pragma unroll
    for (int d = 8; d > 0; d >>= 1) {
#pragma unroll
        for (int i = 0; i < 16; i++) {
            if (i < d) {
                float give = (l16 & d) ? v[i] : v[i + d];
                float got  = __shfl_xor_sync(0xffffffffu, give, d);
                float keep = (l16 & d) ? v[i + d] : v[i];
                v[i] = keep + got;
            }
        }
    }
    return v[0];
}

// ---------------------------------------------------------------------------
// Kernel 1: e_v for ALL words: out[b][w] = exp(tanh(x_v[b].W_V[w] + b_V[w]))
// Per-warp cp.async pipeline: warp owns 8 words, private 3-stage smem ring,
// no CTA barriers in steady state. Lanes 0-15 accumulate batches 0-3,
// lanes 16-31 batches 4-7 (identical W reads -> broadcast).
// ---------------------------------------------------------------------------
__global__ void __launch_bounds__(256, 2) ev_main_kernel(
    const float* __restrict__ gru,   // [B, H]
    const float* __restrict__ emb,   // [B, E]
    const float* __restrict__ W_V,   // [V, XV]
    const float* __restrict__ b_V,   // [V]
    float* __restrict__ out)         // [B, V]
{
    extern __shared__ __align__(16) float dsm[];
    float* xs    = dsm;                                    // [8][1536]
    float* rings = dsm + BATCH * XV;                       // [8][DEPTH][STAGEF]
    float* rs    = rings + WARPS_PER_CTA * DEPTH * STAGEF; // [8]

    int tid = threadIdx.x;
    if (tid < BATCH) rs[tid] = 0.0f;
    for (int i = tid; i < BATCH * XV / 4; i += 256) {
        int idx = i * 4;
        int b = idx / XV;
        int c = idx - b * XV;
        float4 v;
        if (c < HDIM) v = *(const float4*)&gru[b * HDIM + c];
        else          v = *(const float4*)&emb[b * EDIM + (c - HDIM)];
        *(float4*)&xs[b * XV + c] = v;
    }
    __syncthreads();

    int warp  = tid >> 5;
    int lane  = tid & 31;
    int half  = lane >> 4;
    int l16   = lane & 15;
    int bbase = half * 4;
    int lc    = l16 * 4;
    int myb   = bbase + (l16 & 3);
    float rsum = 0.0f;

    float* ring = rings + warp * (DEPTH * STAGEF);

    // per-lane cp.async offsets: 4 x 16B per stage (8 words x 16 float4)
    int goff[4], soff[4];
#pragma unroll
    for (int j = 0; j < 4; j++) {
        int f    = lane + 32 * j;
        int word = f >> 4;
        int col4 = f & 15;
        goff[j] = word * XV + col4 * 4;   // + chunk*64 at use site
        soff[j] = word * 64 + col4 * 4;
    }

    int t = 0, tn = 0;
    if (lane == 0) t = atomicAdd(&g_tile, 1);
    t = __shfl_sync(0xffffffffu, t, 0);
    if (lane == 0) tn = atomicAdd(&g_tile, 1);
    tn = __shfl_sync(0xffffffffu, tn, 0);

    const float* Wt = W_V + (size_t)t * (NW * XV);

    // prologue: stages 0..DEPTH-1 of first tile
#pragma unroll
    for (int s = 0; s < DEPTH; s++) {
        if (t < TILES) {
#pragma unroll
            for (int j = 0; j < 4; j++)
                cp16(ring + s * STAGEF + soff[j], Wt + s * 64 + goff[j]);
        }
        CP_COMMIT();
    }

    while (t < TILES) {
        const float* Wn = W_V + (size_t)tn * (NW * XV);

        u64 acc[NW][4];
#pragma unroll
        for (int wi = 0; wi < NW; wi++)
#pragma unroll
            for (int bi = 0; bi < 4; bi++) acc[wi][bi] = 0ull;

#pragma unroll 6
        for (int c = 0; c < NSTAGES; c++) {
            CP_WAIT(DEPTH - 1);
            __syncwarp();

            const float* rg = ring + (c % DEPTH) * STAGEF;
            int xc = c * 64 + lc;
            ulonglong2 x0 = *(const ulonglong2*)&xs[(bbase + 0) * XV + xc];
            ulonglong2 x1 = *(const ulonglong2*)&xs[(bbase + 1) * XV + xc];
            ulonglong2 x2 = *(const ulonglong2*)&xs[(bbase + 2) * XV + xc];
            ulonglong2 x3 = *(const ulonglong2*)&xs[(bbase + 3) * XV + xc];

#pragma unroll
            for (int wi = 0; wi < NW; wi++) {
                ulonglong2 w = *(const ulonglong2*)&rg[wi * 64 + lc];
                acc[wi][0] = fma2(w.x, x0.x, acc[wi][0]);
                acc[wi][0] = fma2(w.y, x0.y, acc[wi][0]);
                acc[wi][1] = fma2(w.x, x1.x, acc[wi][1]);
                acc[wi][1] = fma2(w.y, x1.y, acc[wi][1]);
                acc[wi][2] = fma2(w.x, x2.x, acc[wi][2]);
                acc[wi][2] = fma2(w.y, x2.y, acc[wi][2]);
                acc[wi][3] = fma2(w.x, x3.x, acc[wi][3]);
                acc[wi][3] = fma2(w.y, x3.y, acc[wi][3]);
            }

            // produce chunk c+DEPTH (this tile or the next) into the slot
            // just consumed; all lanes' LDS above issued before these writes.
            int cn = c + DEPTH;
            if (cn < NSTAGES) {
#pragma unroll
                for (int j = 0; j < 4; j++)
                    cp16(ring + (c % DEPTH) * STAGEF + soff[j],
                         Wt + cn * 64 + goff[j]);
            } else if (tn < TILES) {
                int cc = cn - NSTAGES;
#pragma unroll
                for (int j = 0; j < 4; j++)
                    cp16(ring + (c % DEPTH) * STAGEF + soff[j],
                         Wn + cc * 64 + goff[j]);
            }
            CP_COMMIT();
        }

        // epilogue: fold f32x2 pairs, two 16-value compactions
        float v0[16], v1[16];
#pragma unroll
        for (int wi = 0; wi < 4; wi++)
#pragma unroll
            for (int bi = 0; bi < 4; bi++) {
                v0[wi * 4 + bi] = f2_lo(acc[wi][bi]) + f2_hi(acc[wi][bi]);
                v1[wi * 4 + bi] = f2_lo(acc[wi + 4][bi]) + f2_hi(acc[wi + 4][bi]);
            }
        float s0 = reduce16(v0, l16);   // words w0 + (l16>>2),     batch bbase+(l16&3)
        float s1 = reduce16(v1, l16);   // words w0 + 4 + (l16>>2)

        int w0 = t * NW;
        int wa = w0 + (l16 >> 2);
        int wb = wa + 4;
        float ua = exp_tanh(s0 + __ldg(&b_V[wa]));
        float ub = exp_tanh(s1 + __ldg(&b_V[wb]));
        out[(size_t)myb * VOCAB + wa] = ua;
        out[(size_t)myb * VOCAB + wb] = ub;
        rsum += ua + ub;

        t  = tn;
        Wt = Wn;
        if (lane == 0) tn = atomicAdd(&g_tile, 1);
        tn = __shfl_sync(0xffffffffu, tn, 0);
    }

    atomicAdd(&rs[myb], rsum);
    __syncthreads();
    if (tid < BATCH) atomicAdd(&g_rowsum[tid], rs[tid]);

    if (lane == 0) {
        int d = atomicAdd(&g_done, 1);
        if (d == NWARPS_TOTAL - 1) {
            g_tile = 0;
            __threadfence();
            g_done = 0;
        }
    }
}

// ---------------------------------------------------------------------------
// Kernel 2: fixup topic words (k>0 => v=0 => energy = tanh(k*e_k)).
// One warp per (b,t); first occurrence acts (dedup) and adjusts row sum.
// ---------------------------------------------------------------------------
__global__ void __launch_bounds__(256) ek_fixup_kernel(
    const float* __restrict__ gru,
    const float* __restrict__ emb,
    const float* __restrict__ ctx,
    const int*   __restrict__ topic, // [B, T]
    int T,
    const float* __restrict__ W_K,   // [V, XK]
    const float* __restrict__ b_K,   // [V]
    float* __restrict__ out)
{
    int gw   = (int)((blockIdx.x * blockDim.x + threadIdx.x) >> 5);
    int lane = threadIdx.x & 31;
    if (gw >= BATCH * T) return;
    int b = gw / T;
    int t = gw - b * T;

    int w = topic[b * T + t];
    if (w == 0) return;

    int cnt = 0, first = T;
    for (int tt = lane; tt < T; tt += 32) {
        if (topic[b * T + tt] == w) {
            cnt += 1;
            if (tt < first) first = tt;
        }
    }
#pragma unroll
    for (int o = 16; o > 0; o >>= 1) {
        cnt += __shfl_xor_sync(0xffffffffu, cnt, o);
        int of = __shfl_xor_sync(0xffffffffu, first, o);
        first = of < first ? of : first;
    }
    if (first != t) return;

    const float* Wr = W_K + (size_t)w * XK + lane * 4;
    const int cbase = lane * 4;
    float s = 0.0f;
#pragma unroll
    for (int j = 0; j < XK / 128; ++j) {            // 20 fixed iterations
        int c = cbase + j * 128;
        float4 wv = *(const float4*)&Wr[j * 128];
        float4 xv;
        if (c < HDIM)      xv = *(const float4*)&gru[b * HDIM + c];
        else if (c < XV)   xv = *(const float4*)&emb[b * EDIM + (c - HDIM)];
        else               xv = *(const float4*)&ctx[b * HDIM + (c - XV)];
        s += wv.x * xv.x + wv.y * xv.y + wv.z * xv.z + wv.w * xv.w;
    }
#pragma unroll
    for (int o = 16; o > 0; o >>= 1)
        s += __shfl_xor_sync(0xffffffffu, s, o);

    if (lane == 0) {
        float e   = (float)cnt * (s + b_K[w]);
        float nu  = exp_tanh(e);
        size_t ix = (size_t)b * VOCAB + w;
        float old = out[ix];
        out[ix] = nu;
        atomicAdd(&g_rowsum[b], nu - old);
    }
}

// ---------------------------------------------------------------------------
// Kernel 3: scale by 1/rowsum; last CTA resets g_rowsum for next replay.
// ---------------------------------------------------------------------------
__global__ void __launch_bounds__(256) norm_kernel(float* __restrict__ out)
{
    int b     = blockIdx.x / NORM_SLICES;
    int slice = blockIdx.x % NORM_SLICES;
    float inv = 1.0f / g_rowsum[b];

    const int per = VOCAB / NORM_SLICES;          // 2000
    float* seg = out + (size_t)b * VOCAB + slice * per;
    for (int i = threadIdx.x * 4; i < per; i += 256 * 4) {
        float4 v = *(const float4*)&seg[i];
        v.x *= inv; v.y *= inv; v.z *= inv; v.w *= inv;
        *(float4*)&seg[i] = v;
    }

    __syncthreads();
    if (threadIdx.x == 0) {
        int d = atomicAdd(&g_norm_done, 1);
        if (d == NORM_GRID - 1) {
            for (int i = 0; i < BATCH; i++) g_rowsum[i] = 0.0f;
            __threadfence();
            g_norm_done = 0;
        }
    }
}

// ---------------------------------------------------------------------------
extern "C" void kernel_launch(void* const* d_in, const int* in_sizes, int n_in,
                              void* d_out, int out_size)
{
    const float* gru   = (const float*)d_in[0];
    const float* emb   = (const float*)d_in[1];
    const float* ctx   = (const float*)d_in[2];
    const int*   topic = (const int*)d_in[3];
    int T = in_sizes[3] / BATCH;

    const float* W_V = nullptr; const float* b_V = nullptr;
    const float* W_K = nullptr; const float* b_K = nullptr;
    for (int i = 4; i < n_in; ++i) {
        long sz = (long)in_sizes[i];
        if (sz == (long)VOCAB * XV && i + 1 < n_in) {
            W_V = (const float*)d_in[i];
            b_V = (const float*)d_in[i + 1];
        } else if (sz == (long)VOCAB * XK && i + 1 < n_in) {
            W_K = (const float*)d_in[i];
            b_K = (const float*)d_in[i + 1];
        }
    }

    float* out = (float*)d_out;

    static bool attr_set = false;
    if (!attr_set) {
        cudaFuncSetAttribute(ev_main_kernel,
                             cudaFuncAttributeMaxDynamicSharedMemorySize,
                             SMEM_BYTES);
        attr_set = true;
    }

    ev_main_kernel<<<CTAS, 256, SMEM_BYTES>>>(gru, emb, W_V, b_V, out);

    int nwarps  = BATCH * T;
    int nblocks = (nwarps * 32 + 255) / 256;
    ek_fixup_kernel<<<nblocks, 256>>>(gru, emb, ctx, topic, T, W_K, b_K, out);

    norm_kernel<<<NORM_GRID, 256>>>(out);
}

// round 8
// speedup vs baseline: 1.3359x; 1.0829x over previous
#include <cuda_runtime.h>
#include <math.h>

// Problem constants: B=8, H=1024, E=512, V=32000, T=100
#define VOCAB 32000
#define BATCH 8
#define HDIM  1024
#define EDIM  512
#define XV    (HDIM + EDIM)        // 1536
#define XK    (2 * HDIM + EDIM)    // 2560

#define NW      4                  // words per tile
#define TILES   (VOCAB / NW)       // 8000
#define DEPTH   6                  // cp.async ring stages per warp
#define STAGEF  (NW * 64)          // floats per stage (4 words x 64 cols) = 1KB
#define NSTAGES (XV / 64)          // 24 column-chunks
#define CTAS    296                // 148 SMs x 2 CTAs
#define WARPS_PER_CTA 8
#define NWARPS_TOTAL (CTAS * WARPS_PER_CTA)   // 2368
#define NORM_SLICES 16
#define NORM_GRID (BATCH * NORM_SLICES)

// dynamic smem: xs[8][1536] | rings[8 warps][DEPTH][STAGEF] | rs[8]
#define SMEM_FLOATS (BATCH * XV + WARPS_PER_CTA * DEPTH * STAGEF + 8)
#define SMEM_BYTES  (SMEM_FLOATS * 4)

typedef unsigned long long u64;

__device__ __forceinline__ u64 fma2(u64 a, u64 b, u64 c) {
    u64 d;
    asm("fma.rn.f32x2 %0, %1, %2, %3;" : "=l"(d) : "l"(a), "l"(b), "l"(c));
    return d;
}
__device__ __forceinline__ float f2_lo(u64 a) { return __uint_as_float((unsigned)a); }
__device__ __forceinline__ float f2_hi(u64 a) { return __uint_as_float((unsigned)(a >> 32)); }

__device__ __forceinline__ float exp_tanh(float e) {
    float ec = fminf(fmaxf(e, -9.0f), 9.0f);
    float t  = __expf(2.0f * ec);
    float th = (t - 1.0f) / (t + 1.0f);
    return __expf(th);
}

__device__ __forceinline__ void cp16(float* smem_dst, const float* gmem_src) {
    unsigned s = (unsigned)__cvta_generic_to_shared(smem_dst);
    asm volatile("cp.async.cg.shared.global [%0], [%1], 16;\n"
                 :: "r"(s), "l"(gmem_src) : "memory");
}
#define CP_COMMIT() asm volatile("cp.async.commit_group;\n" ::: "memory")
#define CP_WAIT(N)  asm volatile("cp.async.wait_group %0;\n" :: "n"(N) : "memory")

// device state: only softmax row sums (self-resetting via norm kernel)
__device__ float g_rowsum[BATCH] = {};
__device__ int   g_norm_done = 0;

// 16-value compacting butterfly across a half-warp (15 shuffles).
// Lane l16 ends holding the full sum for index l16.
__device__ __forceinline__ float reduce16(float* v, int l16) {
#pragma unroll
    for (int d = 8; d > 0; d >>= 1) {
#pragma unroll
        for (int i = 0; i < 16; i++) {
            if (i < d) {
                float give = (l16 & d) ? v[i] : v[i + d];
                float got  = __shfl_xor_sync(0xffffffffu, give, d);
                float keep = (l16 & d) ? v[i + d] : v[i];
                v[i] = keep + got;
            }
        }
    }
    return v[0];
}

// ---------------------------------------------------------------------------
// Kernel 1: e_v for ALL words: out[b][w] = exp(tanh(x_v[b].W_V[w] + b_V[w]))
// STATIC cyclic tile schedule (zero scheduling atomics). Warp owns 4 words,
// private 6-stage cp.async smem ring, no CTA barriers in steady state.
// Lanes 0-15 accumulate batches 0-3, lanes 16-31 batches 4-7.
// ---------------------------------------------------------------------------
__global__ void __launch_bounds__(256, 2) ev_main_kernel(
    const float* __restrict__ gru,   // [B, H]
    const float* __restrict__ emb,   // [B, E]
    const float* __restrict__ W_V,   // [V, XV]
    const float* __restrict__ b_V,   // [V]
    float* __restrict__ out)         // [B, V]
{
    extern __shared__ __align__(16) float dsm[];
    float* xs    = dsm;                                    // [8][1536]
    float* rings = dsm + BATCH * XV;                       // [8][DEPTH][STAGEF]
    float* rs    = rings + WARPS_PER_CTA * DEPTH * STAGEF; // [8]

    int tid = threadIdx.x;
    if (tid < BATCH) rs[tid] = 0.0f;
    for (int i = tid; i < BATCH * XV / 4; i += 256) {
        int idx = i * 4;
        int b = idx / XV;
        int c = idx - b * XV;
        float4 v;
        if (c < HDIM) v = *(const float4*)&gru[b * HDIM + c];
        else          v = *(const float4*)&emb[b * EDIM + (c - HDIM)];
        *(float4*)&xs[b * XV + c] = v;
    }
    __syncthreads();

    int warp  = tid >> 5;
    int lane  = tid & 31;
    int half  = lane >> 4;
    int l16   = lane & 15;
    int bbase = half * 4;
    int lc    = l16 * 4;
    int myb   = bbase + (l16 & 3);
    int gw    = blockIdx.x * WARPS_PER_CTA + warp;   // 0..2367
    float rsum = 0.0f;

    float* ring = rings + warp * (DEPTH * STAGEF);

    // per-lane cp.async offsets: 2 x 16B per stage (4 words x 16 float4)
    int goff[2], soff[2];
#pragma unroll
    for (int j = 0; j < 2; j++) {
        int f    = lane + 32 * j;
        int word = f >> 4;        // 0..3
        int col4 = f & 15;        // 0..15
        goff[j] = word * XV + col4 * 4;   // + chunk*64 at use site
        soff[j] = word * 64 + col4 * 4;
    }

    int t = gw;
    const float* Wt = W_V + (size_t)t * (NW * XV);

    // prologue: fill DEPTH stages from first tile (guarded)
#pragma unroll
    for (int s = 0; s < DEPTH; s++) {
        if (t < TILES) {
#pragma unroll
            for (int j = 0; j < 2; j++)
                cp16(ring + s * STAGEF + soff[j], Wt + s * 64 + goff[j]);
        }
        CP_COMMIT();
    }

    while (t < TILES) {
        int tn = t + NWARPS_TOTAL;                    // statically known
        const float* Wn = W_V + (size_t)tn * (NW * XV);
        bool nvalid = tn < TILES;

        u64 acc[NW][4];
#pragma unroll
        for (int wi = 0; wi < NW; wi++)
#pragma unroll
            for (int bi = 0; bi < 4; bi++) acc[wi][bi] = 0ull;

#pragma unroll 8
        for (int c = 0; c < NSTAGES; c++) {
            CP_WAIT(DEPTH - 1);
            __syncwarp();

            const float* rg = ring + (c % DEPTH) * STAGEF;
            int xc = c * 64 + lc;
            ulonglong2 x0 = *(const ulonglong2*)&xs[(bbase + 0) * XV + xc];
            ulonglong2 x1 = *(const ulonglong2*)&xs[(bbase + 1) * XV + xc];
            ulonglong2 x2 = *(const ulonglong2*)&xs[(bbase + 2) * XV + xc];
            ulonglong2 x3 = *(const ulonglong2*)&xs[(bbase + 3) * XV + xc];

#pragma unroll
            for (int wi = 0; wi < NW; wi++) {
                ulonglong2 w = *(const ulonglong2*)&rg[wi * 64 + lc];
                acc[wi][0] = fma2(w.x, x0.x, acc[wi][0]);
                acc[wi][0] = fma2(w.y, x0.y, acc[wi][0]);
                acc[wi][1] = fma2(w.x, x1.x, acc[wi][1]);
                acc[wi][1] = fma2(w.y, x1.y, acc[wi][1]);
                acc[wi][2] = fma2(w.x, x2.x, acc[wi][2]);
                acc[wi][2] = fma2(w.y, x2.y, acc[wi][2]);
                acc[wi][3] = fma2(w.x, x3.x, acc[wi][3]);
                acc[wi][3] = fma2(w.y, x3.y, acc[wi][3]);
            }

            // refill the just-consumed slot with chunk c+DEPTH (this tile or next)
            int cn = c + DEPTH;
            if (cn < NSTAGES) {
#pragma unroll
                for (int j = 0; j < 2; j++)
                    cp16(ring + (c % DEPTH) * STAGEF + soff[j],
                         Wt + cn * 64 + goff[j]);
            } else if (nvalid) {
                int cc = cn - NSTAGES;
#pragma unroll
                for (int j = 0; j < 2; j++)
                    cp16(ring + (c % DEPTH) * STAGEF + soff[j],
                         Wn + cc * 64 + goff[j]);
            }
            CP_COMMIT();
        }

        // epilogue: fold f32x2 pairs, one 16-value compaction per half-warp
        float v[16];
#pragma unroll
        for (int wi = 0; wi < NW; wi++)
#pragma unroll
            for (int bi = 0; bi < 4; bi++)
                v[wi * 4 + bi] = f2_lo(acc[wi][bi]) + f2_hi(acc[wi][bi]);
        float s0 = reduce16(v, l16);     // word t*4+(l16>>2), batch bbase+(l16&3)

        int word = t * NW + (l16 >> 2);
        float u  = exp_tanh(s0 + __ldg(&b_V[word]));
        out[(size_t)myb * VOCAB + word] = u;
        rsum += u;

        t  = tn;
        Wt = Wn;
    }

    // per-CTA row-sum reduction -> 8 global atomics
    atomicAdd(&rs[myb], rsum);
    __syncthreads();
    if (tid < BATCH) atomicAdd(&g_rowsum[tid], rs[tid]);
}

// ---------------------------------------------------------------------------
// Kernel 2: fixup topic words (k>0 => v=0 => energy = tanh(k*e_k)).
// One warp per (b,t); first occurrence acts (dedup) and adjusts row sum.
// ---------------------------------------------------------------------------
__global__ void __launch_bounds__(256) ek_fixup_kernel(
    const float* __restrict__ gru,
    const float* __restrict__ emb,
    const float* __restrict__ ctx,
    const int*   __restrict__ topic, // [B, T]
    int T,
    const float* __restrict__ W_K,   // [V, XK]
    const float* __restrict__ b_K,   // [V]
    float* __restrict__ out)
{
    int gw   = (int)((blockIdx.x * blockDim.x + threadIdx.x) >> 5);
    int lane = threadIdx.x & 31;
    if (gw >= BATCH * T) return;
    int b = gw / T;
    int t = gw - b * T;

    int w = topic[b * T + t];
    if (w == 0) return;

    int cnt = 0, first = T;
    for (int tt = lane; tt < T; tt += 32) {
        if (topic[b * T + tt] == w) {
            cnt += 1;
            if (tt < first) first = tt;
        }
    }
#pragma unroll
    for (int o = 16; o > 0; o >>= 1) {
        cnt += __shfl_xor_sync(0xffffffffu, cnt, o);
        int of = __shfl_xor_sync(0xffffffffu, first, o);
        first = of < first ? of : first;
    }
    if (first != t) return;

    const float* Wr = W_K + (size_t)w * XK + lane * 4;
    const int cbase = lane * 4;
    float s = 0.0f;
#pragma unroll
    for (int j = 0; j < XK / 128; ++j) {            // 20 fixed iterations
        int c = cbase + j * 128;
        float4 wv = *(const float4*)&Wr[j * 128];
        float4 xv;
        if (c < HDIM)      xv = *(const float4*)&gru[b * HDIM + c];
        else if (c < XV)   xv = *(const float4*)&emb[b * EDIM + (c - HDIM)];
        else               xv = *(const float4*)&ctx[b * HDIM + (c - XV)];
        s += wv.x * xv.x + wv.y * xv.y + wv.z * xv.z + wv.w * xv.w;
    }
#pragma unroll
    for (int o = 16; o > 0; o >>= 1)
        s += __shfl_xor_sync(0xffffffffu, s, o);

    if (lane == 0) {
        float e   = (float)cnt * (s + b_K[w]);
        float nu  = exp_tanh(e);
        size_t ix = (size_t)b * VOCAB + w;
        float old = out[ix];
        out[ix] = nu;
        atomicAdd(&g_rowsum[b], nu - old);
    }
}

// ---------------------------------------------------------------------------
// Kernel 3: scale by 1/rowsum; last CTA resets g_rowsum for next replay.
// ---------------------------------------------------------------------------
__global__ void __launch_bounds__(256) norm_kernel(float* __restrict__ out)
{
    int b     = blockIdx.x / NORM_SLICES;
    int slice = blockIdx.x % NORM_SLICES;
    float inv = 1.0f / g_rowsum[b];

    const int per = VOCAB / NORM_SLICES;          // 2000
    float* seg = out + (size_t)b * VOCAB + slice * per;
    for (int i = threadIdx.x * 4; i < per; i += 256 * 4) {
        float4 v = *(const float4*)&seg[i];
        v.x *= inv; v.y *= inv; v.z *= inv; v.w *= inv;
        *(float4*)&seg[i] = v;
    }

    __syncthreads();
    if (threadIdx.x == 0) {
        int d = atomicAdd(&g_norm_done, 1);
        if (d == NORM_GRID - 1) {
            for (int i = 0; i < BATCH; i++) g_rowsum[i] = 0.0f;
            __threadfence();
            g_norm_done = 0;
        }
    }
}

// ---------------------------------------------------------------------------
extern "C" void kernel_launch(void* const* d_in, const int* in_sizes, int n_in,
                              void* d_out, int out_size)
{
    const float* gru   = (const float*)d_in[0];
    const float* emb   = (const float*)d_in[1];
    const float* ctx   = (const float*)d_in[2];
    const int*   topic = (const int*)d_in[3];
    int T = in_sizes[3] / BATCH;

    const float* W_V = nullptr; const float* b_V = nullptr;
    const float* W_K = nullptr; const float* b_K = nullptr;
    for (int i = 4; i < n_in; ++i) {
        long sz = (long)in_sizes[i];
        if (sz == (long)VOCAB * XV && i + 1 < n_in) {
            W_V = (const float*)d_in[i];
            b_V = (const float*)d_in[i + 1];
        } else if (sz == (long)VOCAB * XK && i + 1 < n_in) {
            W_K = (const float*)d_in[i];
            b_K = (const float*)d_in[i + 1];
        }
    }

    float* out = (float*)d_out;

    static bool attr_set = false;
    if (!attr_set) {
        cudaFuncSetAttribute(ev_main_kernel,
                             cudaFuncAttributeMaxDynamicSharedMemorySize,
                             SMEM_BYTES);
        attr_set = true;
    }

    ev_main_kernel<<<CTAS, 256, SMEM_BYTES>>>(gru, emb, W_V, b_V, out);

    int nwarps  = BATCH * T;
    int nblocks = (nwarps * 32 + 255) / 256;
    ek_fixup_kernel<<<nblocks, 256>>>(gru, emb, ctx, topic, T, W_K, b_K, out);

    norm_kernel<<<NORM_GRID, 256>>>(out);
}